// round 13
// baseline (speedup 1.0000x reference)
#include <cuda_runtime.h>
#include <cstdint>

// GSHashEncoding: out[p,:] = concat(gather(code0, map0[p,:]), gather(code1, map1[p,:])) @ W
// Warp-autonomous version: each warp gathers + matvecs + stores its own 32 points.

#define L0_SIZE   65536
#define RESO      2097152
#define NPB       256
#define FSTRIDE   9        // s_feats row stride (coprime with 32 -> conflict-free STS/LDS)

__device__ __forceinline__ unsigned long long pack2(float lo, float hi) {
    unsigned long long r;
    asm("mov.b64 %0, {%1, %2};" : "=l"(r) : "f"(lo), "f"(hi));
    return r;
}
__device__ __forceinline__ void unpack2(unsigned long long v, float& lo, float& hi) {
    asm("mov.b64 {%0, %1}, %2;" : "=f"(lo), "=f"(hi) : "l"(v));
}
// d = a * b + d   (packed 2x fp32)
__device__ __forceinline__ void fma2(unsigned long long& d, unsigned long long a, unsigned long long b) {
    asm("fma.rn.f32x2 %0, %1, %2, %0;" : "+l"(d) : "l"(a), "l"(b));
}

__global__ void __launch_bounds__(256, 4) gshash_kernel(
    const float* __restrict__ codes,
    const float* __restrict__ W,
    const int*   __restrict__ map0,
    const int*   __restrict__ map1,
    float*       __restrict__ out)
{
    __shared__ float s_feats[NPB * FSTRIDE];   // 9 KB, padded rows

    const int tid  = threadIdx.x;
    const int lane = tid & 31;
    const int w    = tid >> 5;
    const int g    = lane & 7;                 // owns contiguous cols 6g..6g+5
    const int s    = lane >> 3;                // point slot within pass (0..3)
    const long long pbase = (long long)blockIdx.x * NPB;

    // ---- W slice: 3 adjacent col-pairs (6g+2j, 6g+2j+1) per k, packed f32x2 ----
    unsigned long long w2[8][3];
#pragma unroll
    for (int k = 0; k < 8; k++) {
#pragma unroll
        for (int j = 0; j < 3; j++) {
            float2 wv = *(const float2*)(W + k * 48 + 6 * g + 2 * j);
            w2[k][j] = pack2(wv.x, wv.y);
        }
    }

    // ---- Phase A: each lane gathers 8 feats for its own point ----
    {
        long long p = pbase + tid;
        int4 m0 = ((const int4*)map0)[p];
        int4 m1 = ((const int4*)map1)[p];
        const float* c1 = codes + (size_t)L0_SIZE * 4;
        float f[8];
        f[0] = __ldg(codes + (size_t)m0.x * 4 + 0);
        f[1] = __ldg(codes + (size_t)m0.y * 4 + 1);
        f[2] = __ldg(codes + (size_t)m0.z * 4 + 2);
        f[3] = __ldg(codes + (size_t)m0.w * 4 + 3);
        f[4] = __ldg(c1 + (size_t)m1.x * 4 + 0);
        f[5] = __ldg(c1 + (size_t)m1.y * 4 + 1);
        f[6] = __ldg(c1 + (size_t)m1.z * 4 + 2);
        f[7] = __ldg(c1 + (size_t)m1.w * 4 + 3);
        float* sf = s_feats + tid * FSTRIDE;   // lane*9 mod 32 all distinct -> conflict-free
#pragma unroll
        for (int k = 0; k < 8; k++) sf[k] = f[k];
    }
    __syncwarp();                              // warp-local producer/consumer only

    // ---- Phase B: 8 passes of 4 points; shuffle-permuted linear STG.64 ----
    const float* sbase = s_feats + w * 32 * FSTRIDE;
    float2* outw = (float2*)(out + (pbase + (long long)w * 32) * 48);

#pragma unroll
    for (int i = 0; i < 8; i++) {
        const float* sfp = sbase + (4 * i + s) * FSTRIDE;
        unsigned long long acc0 = 0ull, acc1 = 0ull, acc2 = 0ull;
#pragma unroll
        for (int k = 0; k < 8; k++) {
            float fv = sfp[k];                 // 4 addrs, 8-lane broadcast, conflict-free
            unsigned long long f2v = pack2(fv, fv);
            fma2(acc0, f2v, w2[k][0]);
            fma2(acc1, f2v, w2[k][1]);
            fma2(acc2, f2v, w2[k][2]);
        }
        float a0, a1, a2, a3, a4, a5;
        unpack2(acc0, a0, a1);                 // cols 6g, 6g+1 of point 4i+s
        unpack2(acc1, a2, a3);                 // cols 6g+2, 6g+3
        unpack2(acc2, a4, a5);                 // cols 6g+4, 6g+5

        // Permute: element e = 32r + lane is float2 #e of this pass's 768B region.
        // e -> (point pe = e/24, colpair cp = e%24); owner lane = pe*8 + cp/3, pair j = cp%3.
#pragma unroll
        for (int r = 0; r < 3; r++) {
            int e  = 32 * r + lane;
            int pe = e / 24;
            int cp = e - 24 * pe;
            int gs = cp / 3;
            int js = cp - 3 * gs;
            int src = pe * 8 + gs;
            float v0 = __shfl_sync(0xffffffffu, a0, src);
            float v1 = __shfl_sync(0xffffffffu, a1, src);
            float v2 = __shfl_sync(0xffffffffu, a2, src);
            float v3 = __shfl_sync(0xffffffffu, a3, src);
            float v4 = __shfl_sync(0xffffffffu, a4, src);
            float v5 = __shfl_sync(0xffffffffu, a5, src);
            float lo = (js == 0) ? v0 : (js == 1) ? v2 : v4;
            float hi = (js == 0) ? v1 : (js == 1) ? v3 : v5;
            outw[i * 96 + e] = make_float2(lo, hi);   // 32 lanes -> 256B contiguous
        }
    }
}

extern "C" void kernel_launch(void* const* d_in, const int* in_sizes, int n_in,
                              void* d_out, int out_size) {
    const float* codes = (const float*)d_in[0];
    const float* W     = (const float*)d_in[1];
    const int*   map0  = (const int*)d_in[2];
    const int*   map1  = (const int*)d_in[3];
    float*       outp  = (float*)d_out;

    (void)in_sizes; (void)n_in; (void)out_size;
    gshash_kernel<<<RESO / NPB, 256>>>(codes, W, map0, map1, outp);
}